// round 1
// baseline (speedup 1.0000x reference)
#include <cuda_runtime.h>

// NeuromorphicNetwork: the reference's "time = spike_count" semantics mean every
// neuron spikes at most once EVER (after the first spike, t - last == 1, never
// > refractory=1). Threshold never adapts (count <= 1 < 10). So the exact
// simulation needs only (v, active) per neuron, and spike decisions have ~1000x
// margin vs threshold, making the Bernoulli sampling replaceable by its
// expectation sigmoid(x) without changing any decision (hence identical output).
//
// Persistent single kernel: batch loop with software grid barrier (148 blocks,
// single wave guaranteed), early exit once no hidden neuron is active.

#define NB 148
#define NT 1024
#define BATCH 512
#define INDIM 4096
#define HID 8192
#define OUTDIM 1024
#define TSTEPS 10
#define LEAK 0.95f

// -------- scratch (static __device__: no allocations allowed) --------
__device__ float g_part1[16 * HID];       // GEMV1 partials [slice][h]
__device__ float g_part2[128 * OUTDIM];   // GEMV2 partials [slice][o]
__device__ float g_vh[HID];
__device__ int   g_acth[HID];
__device__ float g_hflag[HID];            // spiked this batch (0/1)
__device__ float g_vo[OUTDIM];
__device__ int   g_acto[OUTDIM];
__device__ int   g_cnt_spk;               // hidden spikes this batch
__device__ int   g_cnt_act;               // remaining active hidden neurons
__device__ int   g_exit;
__device__ unsigned g_bar_cnt;
__device__ volatile unsigned g_bar_gen;

__device__ __forceinline__ void grid_barrier() {
    __threadfence();                 // make this thread's prior global writes visible
    __syncthreads();
    if (threadIdx.x == 0) {
        unsigned gen = g_bar_gen;    // stable: barrier can't release before my add
        if (atomicAdd(&g_bar_cnt, 1u) == NB - 1u) {
            g_bar_cnt = 0;           // reset before release (all have arrived)
            __threadfence();
            g_bar_gen = gen + 1u;
        } else {
            while (g_bar_gen == gen) __nanosleep(64);
        }
    }
    __syncthreads();
}

extern "C" __global__ void __launch_bounds__(NT, 1)
snn_kernel(const float* __restrict__ x,
           const float* __restrict__ Wih,
           const float* __restrict__ Who,
           float* __restrict__ out)
{
    __shared__ float ssm[256];   // sigmoid(x) slice for GEMV1
    __shared__ float hfs[64];    // hidden spike flags slice for GEMV2

    const int tid = threadIdx.x;
    const int bid = blockIdx.x;
    const int g   = bid * NT + tid;

    // ---- init (must run every launch: deterministic, graph-replayable) ----
    if (g < HID)    { g_vh[g] = 0.0f; g_acth[g] = 1; }
    if (g < OUTDIM) { g_vo[g] = 0.0f; g_acto[g] = 1; }
    if (g == 0)     { g_exit = 0; g_cnt_spk = 0; g_cnt_act = HID; }
    grid_barrier();

    for (int b = 0; b < BATCH; b++) {
        // ---- P1: GEMV1 partials: cur_h = sigmoid(x[b]) @ W_ih ----
        // 128 blocks: slice = bid>>3 covers j in [slice*256, +256),
        // h = (bid&7)*1024 + tid. Each W_ih element read exactly once.
        if (bid < 128) {
            const int slice = bid >> 3;
            const int h     = ((bid & 7) << 10) + tid;
            const int j0    = slice << 8;
            if (tid < 256) {
                float xv = x[b * INDIM + j0 + tid];
                ssm[tid] = 1.0f / (1.0f + __expf(-xv));
            }
            __syncthreads();
            const float* wp = Wih + j0 * HID + h;
            float acc = 0.0f;
            #pragma unroll 8
            for (int j = 0; j < 256; j++)
                acc += ssm[j] * wp[j * HID];
            g_part1[slice * HID + h] = acc;
        } else if (bid == 128 && tid == 0) {
            g_cnt_spk = 0;   // per-batch spike counter reset
        }
        grid_barrier();

        // ---- P2: reduce partials + exact hidden integrate-and-fire ----
        if (g < HID) {
            const int h = g;
            float c = 0.0f;
            #pragma unroll
            for (int sl = 0; sl < 16; sl++)
                c += __ldcg(&g_part1[sl * HID + h]);
            float hf = 0.0f;
            if (g_acth[h]) {
                float v = g_vh[h];
                #pragma unroll
                for (int t = 0; t < TSTEPS; t++) {
                    v = v * LEAK + c;
                    if (v >= 1.0f) { hf = 1.0f; break; }
                }
                if (hf != 0.0f) {
                    g_acth[h] = 0;               // locked forever (refractory)
                    atomicAdd(&g_cnt_spk, 1);
                    atomicSub(&g_cnt_act, 1);
                } else {
                    g_vh[h] = v;                 // carry membrane potential
                }
            }
            g_hflag[h] = hf;
        }
        grid_barrier();

        const int S = __ldcg(&g_cnt_spk);

        // ---- P3: GEMV2 partials: cur_o = 0.1 * sum_{spiked h} W_ho[h,:] ----
        if (S > 0 && bid < 128) {
            const int h0 = bid << 6;    // 64 h per block
            if (tid < 64) hfs[tid] = __ldcg(&g_hflag[h0 + tid]);
            __syncthreads();
            const float* wp = Who + h0 * OUTDIM + tid;   // o = tid
            float acc = 0.0f;
            #pragma unroll 8
            for (int k = 0; k < 64; k++)
                acc += hfs[k] * wp[k * OUTDIM];
            g_part2[bid * OUTDIM + tid] = acc * 0.1f;
        }
        grid_barrier();

        // ---- P4: reduce + output integrate-and-fire + write row ----
        if (bid == 0) {
            const int o = tid;
            float c = 0.0f;
            if (S > 0) {
                #pragma unroll
                for (int sl = 0; sl < 128; sl++)
                    c += __ldcg(&g_part2[sl * OUTDIM + o]);
            }
            float of = 0.0f;
            if (g_acto[o]) {
                float v = g_vo[o];
                #pragma unroll
                for (int t = 0; t < TSTEPS; t++) {
                    v = v * LEAK + c;
                    if (v >= 1.0f) { of = 1.0f; break; }
                }
                if (of != 0.0f) g_acto[o] = 0;
                else            g_vo[o] = v;
            }
            out[b * OUTDIM + o] = of * 0.1f;   // rate decode: nspikes/T
            if (tid == 0) g_exit = (__ldcg(&g_cnt_act) == 0);
        }
        grid_barrier();

        if (__ldcg(&g_exit)) {
            // No active hidden neuron remains: all future hidden spike rates
            // are 0, so cur_o = 0 and un-spiked outputs (v < 1) only decay —
            // every remaining output row is exactly 0.
            const int start = (b + 1) * OUTDIM;
            const int total = BATCH * OUTDIM;
            for (int i = start + g; i < total; i += NB * NT)
                out[i] = 0.0f;
            return;
        }
    }
}

extern "C" void kernel_launch(void* const* d_in, const int* in_sizes, int n_in,
                              void* d_out, int out_size) {
    const float* x   = (const float*)d_in[0];
    const float* Wih = (const float*)d_in[1];
    const float* Who = (const float*)d_in[2];
    (void)in_sizes; (void)n_in; (void)out_size;
    snn_kernel<<<NB, NT>>>(x, Wih, Who, (float*)d_out);
}

// round 2
// speedup vs baseline: 2.5914x; 2.5914x over previous
#include <cuda_runtime.h>

// NeuromorphicNetwork — exact-decision shortcut kernel.
//
// Facts proven from the reference:
//  1) "time" = spike_count, so after a first spike t-last==1, never > refractory
//     (1.0 strict) => every neuron spikes AT MOST ONCE ever. Threshold never
//     adapts (count<=1 < 10), stays 1.0.
//  2) W_ih, W_ho are clipped to [0,1] (non-negative) and all drive terms
//     (sigmoid(x), spike flags) are non-negative => any PARTIAL current sum is
//     a LOWER BOUND of the full current. partial >= thr  =>  full >= thr
//     =>  v1 = v0*leak + c_full >= 1  => spike at the first step, identical to
//     the exact simulation's decision.
//  3) Bernoulli spike sampling replaced by its expectation sigmoid(x): currents
//     ~1024 vs threshold 1, perturbation std ~5 — no decision can flip.
//
// Common path: 256-row subsample of W_ih (8MB) + 512-row subsample of W_ho
// (2MB). If any ACTIVE neuron's partial is below threshold (never happens for
// this data), a fallback computes the full GEMV and exact 10-step dynamics
// (incl. membrane-potential carry), so the kernel stays correct.
//
// Persistent single kernel, 148 blocks (one wave), software grid barrier,
// early exit when no hidden neuron remains active (then all future output
// rows are exactly 0 — prefilled during phase A of batch 0).

#define NB 148
#define NT 1024
#define BATCH 512
#define INDIM 4096
#define HID 8192
#define OUTDIM 1024
#define TSTEPS 10
#define LEAK 0.95f
#define LEAK10 0.5987369392383789f   // 0.95^10
#define THRM 1.0001f                 // provable-spike margin over thr=1.0
#define SUBJ 256                     // W_ih rows sampled (lower bound)
#define SUBH 512                     // W_ho rows sampled (lower bound)

// -------- static scratch (no allocations allowed) --------
__device__ float g_part1[32 * HID];       // GEMV1 partials (32 slices common / 16 fallback)
__device__ float g_part2[128 * OUTDIM];   // GEMV2 partials
__device__ float g_vh[HID];
__device__ int   g_acth[HID];
__device__ float g_hflag[HID];
__device__ float g_vo[OUTDIM];
__device__ int   g_acto[OUTDIM];
__device__ int   g_cnt_spk;               // hidden spikes this batch
__device__ int   g_cnt_act;               // remaining active hidden neurons
__device__ int   g_need_full;             // hidden fallback request
__device__ int   g_need_full_o;           // output fallback request
__device__ int   g_exit;
__device__ unsigned g_bar_cnt;
__device__ volatile unsigned g_bar_gen;

__device__ __forceinline__ void grid_barrier() {
    __threadfence();
    __syncthreads();
    if (threadIdx.x == 0) {
        unsigned gen = g_bar_gen;
        if (atomicAdd(&g_bar_cnt, 1u) == NB - 1u) {
            g_bar_cnt = 0;
            __threadfence();
            g_bar_gen = gen + 1u;
        } else {
            while (g_bar_gen == gen) __nanosleep(64);
        }
    }
    __syncthreads();
}

extern "C" __global__ void __launch_bounds__(NT, 1)
snn_kernel(const float* __restrict__ x,
           const float* __restrict__ Wih,
           const float* __restrict__ Who,
           float* __restrict__ out)
{
    __shared__ float sbuf[256];
    __shared__ int   s_flag;

    const int tid = threadIdx.x;
    const int bid = blockIdx.x;

    for (int b = 0; b < BATCH; b++) {
        // ================= Phase A =================
        // blocks 0..63 : partial GEMV1 over j in [0, SUBJ)   (8 MB read)
        // blocks 64..127 (b==0): zero-prefill entire out     (2 MB write)
        // blocks 128..147 (b==0): init neuron state
        // block 147 tid 0: per-batch scalar resets
        if (bid < 64) {
            const int slice = bid >> 1;             // 0..31, 8 j-rows each
            const int j0    = slice * 8;
            if (tid < 8) {
                float xv = x[b * INDIM + j0 + tid];
                sbuf[tid] = 1.0f / (1.0f + __expf(-xv));
            }
            __syncthreads();
            const int h4 = ((bid & 1) << 10) + tid;  // float4 lane 0..2047
            const float4* W4 = (const float4*)Wih;
            float4 acc = make_float4(0.f, 0.f, 0.f, 0.f);
            #pragma unroll
            for (int j = 0; j < 8; j++) {
                float s = sbuf[j];
                float4 w = W4[(size_t)(j0 + j) * (HID / 4) + h4];
                acc.x += s * w.x; acc.y += s * w.y;
                acc.z += s * w.z; acc.w += s * w.w;
            }
            ((float4*)g_part1)[slice * (HID / 4) + h4] = acc;
        } else if (b == 0) {
            if (bid < 128) {
                float4 z = make_float4(0.f, 0.f, 0.f, 0.f);
                int b4 = (bid - 64) * 2048 + tid;    // 64 blocks * 2048 fl4 = whole out
                ((float4*)out)[b4]        = z;
                ((float4*)out)[b4 + 1024] = z;
            } else {
                int g = (bid - 128) * NT + tid;      // 20 blocks cover 9216 slots
                if (g < HID)                       { g_vh[g] = 0.f; g_acth[g] = 1; }
                else if (g < HID + OUTDIM)         { int o = g - HID; g_vo[o] = 0.f; g_acto[o] = 1; }
            }
        }
        if (bid == 147 && tid == 0) {
            if (b == 0) g_cnt_act = HID;
            g_cnt_spk = 0; g_need_full = 0; g_need_full_o = 0; g_exit = 0;
        }
        grid_barrier();

        // ================= Phase B: hidden decisions =================
        if (bid < 8) {
            const int h = bid * NT + tid;
            float c = 0.f;
            #pragma unroll
            for (int sl = 0; sl < 32; sl++) c += __ldcg(&g_part1[sl * HID + h]);
            const int act = g_acth[h];
            const bool spike = act && (c >= THRM);     // provable: lower bound >= thr
            const bool needf = act && !(c >= THRM);    // can't decide -> exact fallback
            if (spike) g_acth[h] = 0;
            g_hflag[h] = spike ? 1.0f : 0.0f;
            unsigned ms = __ballot_sync(0xffffffffu, spike);
            if ((tid & 31) == 0 && ms) {
                atomicAdd(&g_cnt_spk, __popc(ms));
                atomicSub(&g_cnt_act, __popc(ms));
            }
            unsigned mf = __ballot_sync(0xffffffffu, needf);
            if ((tid & 31) == 0 && mf) atomicExch(&g_need_full, 1);
        }
        grid_barrier();

        // ---------- hidden fallback: full GEMV + exact dynamics ----------
        if (__ldcg(&g_need_full)) {
            if (bid < 128) {                    // full GEMV1: 16 slices * 256 j
                const int slice = bid >> 3;
                const int j0    = slice << 8;
                const int h     = ((bid & 7) << 10) + tid;
                if (tid < 256) {
                    float xv = x[b * INDIM + j0 + tid];
                    sbuf[tid] = 1.0f / (1.0f + __expf(-xv));
                }
                __syncthreads();
                const float* wp = Wih + (size_t)j0 * HID + h;
                float acc = 0.f;
                #pragma unroll 8
                for (int j = 0; j < 256; j++) acc += sbuf[j] * wp[(size_t)j * HID];
                g_part1[slice * HID + h] = acc;
            }
            grid_barrier();
            if (bid < 8) {                      // exact IF for still-active neurons
                const int h = bid * NT + tid;
                const int act = g_acth[h];
                float c = 0.f;
                #pragma unroll
                for (int sl = 0; sl < 16; sl++) c += __ldcg(&g_part1[sl * HID + h]);
                float v = g_vh[h];
                float hf = 0.f;
                #pragma unroll
                for (int t = 0; t < TSTEPS; t++) {
                    v = v * LEAK + c;
                    if (v >= 1.0f) { hf = 1.f; break; }
                }
                const bool spike = act && (hf != 0.f);
                if (spike) { g_acth[h] = 0; g_hflag[h] = 1.0f; }
                else if (act) g_vh[h] = v;      // exact membrane carry
                unsigned ms = __ballot_sync(0xffffffffu, spike);
                if ((tid & 31) == 0 && ms) {
                    atomicAdd(&g_cnt_spk, __popc(ms));
                    atomicSub(&g_cnt_act, __popc(ms));
                }
            }
            grid_barrier();
        }

        // ================= Phase C: partial GEMV2 (first SUBH rows) =================
        {
            const int S = __ldcg(&g_cnt_spk);
            if (S > 0 && bid < 32) {            // 32 blocks * 16 rows = 512 rows
                if (tid < 16) sbuf[tid] = __ldcg(&g_hflag[bid * 16 + tid]);
                __syncthreads();
                const int o4   = tid & 255;
                const int roff = tid >> 8;      // 4 sub-slices of 4 rows
                const float4* W4 = (const float4*)Who;
                float4 acc = make_float4(0.f, 0.f, 0.f, 0.f);
                #pragma unroll
                for (int r = 0; r < 4; r++) {
                    int lr = roff * 4 + r;
                    float f = sbuf[lr];
                    float4 w = W4[(size_t)(bid * 16 + lr) * (OUTDIM / 4) + o4];
                    acc.x += f * w.x; acc.y += f * w.y;
                    acc.z += f * w.z; acc.w += f * w.w;
                }
                ((float4*)g_part2)[(bid * 4 + roff) * (OUTDIM / 4) + o4] = acc;
            }
        }
        grid_barrier();

        // ================= Phase D: output decisions (block 0) =================
        if (bid == 0) {
            if (tid == 0) s_flag = 0;
            __syncthreads();
            const int S = __ldcg(&g_cnt_spk);
            const int o = tid;
            float cp = 0.f;
            if (S > 0) {
                #pragma unroll
                for (int sl = 0; sl < 128; sl++) cp += __ldcg(&g_part2[sl * OUTDIM + o]);
                cp *= 0.1f;                     // lower bound of full cur_o
            }
            if (g_acto[o]) {
                if (S == 0) {
                    g_vo[o] *= LEAK10;          // c==0 exactly: pure decay, no spike (v<1)
                } else if (cp >= THRM) {        // provable spike
                    out[(size_t)b * OUTDIM + o] = 0.1f;
                    g_acto[o] = 0;
                } else {
                    s_flag = 1;                 // undecidable -> output fallback
                }
            }
            __syncthreads();
            if (tid == 0) {
                if (s_flag) { g_need_full_o = 1; g_exit = 0; }
                else        g_exit = (__ldcg(&g_cnt_act) == 0);
            }
        }
        grid_barrier();

        // ---------- output fallback: full GEMV2 + exact dynamics ----------
        if (__ldcg(&g_need_full_o)) {
            if (bid < 128) {                    // full: 128 blocks * 64 rows
                if (tid < 64) sbuf[tid] = __ldcg(&g_hflag[bid * 64 + tid]);
                __syncthreads();
                const float* wp = Who + (size_t)bid * 64 * OUTDIM + tid;
                float acc = 0.f;
                #pragma unroll 8
                for (int k = 0; k < 64; k++) acc += sbuf[k] * wp[(size_t)k * OUTDIM];
                g_part2[bid * OUTDIM + tid] = acc;
            }
            grid_barrier();
            if (bid == 0) {
                const int o = tid;
                float cf = 0.f;
                #pragma unroll
                for (int sl = 0; sl < 128; sl++) cf += __ldcg(&g_part2[sl * OUTDIM + o]);
                cf *= 0.1f;
                if (g_acto[o]) {
                    float v = g_vo[o];
                    float of = 0.f;
                    #pragma unroll
                    for (int t = 0; t < TSTEPS; t++) {
                        v = v * LEAK + cf;
                        if (v >= 1.0f) { of = 1.f; break; }
                    }
                    if (of != 0.f) { out[(size_t)b * OUTDIM + o] = 0.1f; g_acto[o] = 0; }
                    else           g_vo[o] = v;
                }
                __syncthreads();
                if (tid == 0) g_exit = (__ldcg(&g_cnt_act) == 0);
            }
            grid_barrier();
        }

        if (__ldcg(&g_exit)) return;   // remaining rows already prefilled to 0
    }
}

extern "C" void kernel_launch(void* const* d_in, const int* in_sizes, int n_in,
                              void* d_out, int out_size) {
    const float* x   = (const float*)d_in[0];
    const float* Wih = (const float*)d_in[1];
    const float* Who = (const float*)d_in[2];
    (void)in_sizes; (void)n_in; (void)out_size;
    snn_kernel<<<NB, NT>>>(x, Wih, Who, (float*)d_out);
}

// round 7
// speedup vs baseline: 4.2850x; 1.6536x over previous
#include <cuda_runtime.h>

// NeuromorphicNetwork — exact-decision shortcut kernel, v3 (2 barriers/batch).
// (Resubmission: round-3 bench failed on container infra, not the kernel.)
//
// Proven facts (see round-1/2 analysis):
//  1) "time" = spike_count => every neuron spikes at most once ever; threshold
//     never adapts (stays 1.0).
//  2) W_ih, W_ho in [0,1], drives (sigmoid(x), flags) >= 0 => any partial
//     current sum is a LOWER BOUND. partial >= thr => spike at step 0, exactly
//     matching the full simulation (v >= 0 always).
//  3) Bernoulli sampling -> expectation sigmoid(x): currents ~1024 vs thr 1,
//     no decision can flip.
//
// v3 structure (common path, per batch):
//  phase1: blocks 0..63  : 32-row partial GEMV1 over all 8192 h (1 MB)
//          blocks 64..95 : LOCAL re-proof of spike for their 4 hidden rows
//                          (512B of W_ih cols, threshold 1.01 > global 1.0001
//                          + 1e-4 FP-reorder bound => local proof implies the
//                          global proof => flags subset of true spikes =>
//                          output partial remains a lower bound), then
//                          4-row partial GEMV2 (0.5 MB total)
//          blocks 96..147: (b==0) zero-prefill out (2 MB) + init state
//  bar1
//  phase2: blocks 0..7 : global hidden decisions from partials (+counts)
//          block 8     : output decisions from GEMV2 partials, write row
//  bar2
//  exit when no hidden neuron remains active (future rows provably 0).
// Undecidable neurons trigger exact full-GEMV fallbacks (never on this data).

#define NB 148
#define NT 1024
#define BATCH 512
#define INDIM 4096
#define HID 8192
#define OUTDIM 1024
#define TSTEPS 10
#define LEAK 0.95f
#define LEAK10 0.5987369392383789f   // 0.95^10
#define THRM 1.0001f                 // global provable-spike margin
#define THRC 1.01f                   // stricter local-proof margin (FP consistency)

// -------- static scratch --------
__device__ float g_part1[16 * HID];       // 8 slices common / 16 fallback
__device__ float g_part2[128 * OUTDIM];   // 32 slices common / 128 fallback
__device__ float g_vh[HID];
__device__ int   g_acth[HID];
__device__ float g_hflag[HID];
__device__ float g_vo[OUTDIM];
__device__ int   g_acto[OUTDIM];
__device__ int   g_cnt_spk;
__device__ int   g_cnt_act;
__device__ int   g_need_full;
__device__ int   g_retry;
__device__ unsigned g_bar_cnt;
__device__ volatile unsigned g_bar_gen;

__device__ __forceinline__ void grid_barrier() {
    __threadfence();
    __syncthreads();
    if (threadIdx.x == 0) {
        unsigned gen = g_bar_gen;
        if (atomicAdd(&g_bar_cnt, 1u) == NB - 1u) {
            g_bar_cnt = 0;
            __threadfence();
            g_bar_gen = gen + 1u;
        } else {
            while (g_bar_gen == gen) __nanosleep(64);
        }
    }
    __syncthreads();
}

__device__ __forceinline__ float sigm(float v) {
    return 1.0f / (1.0f + __expf(-v));
}

extern "C" __global__ void __launch_bounds__(NT, 1)
snn_kernel(const float* __restrict__ x,
           const float* __restrict__ Wih,
           const float* __restrict__ Who,
           float* __restrict__ out)
{
    __shared__ float sbuf[256];
    __shared__ float sflag[4];

    const int tid = threadIdx.x;
    const int bid = blockIdx.x;

    for (int b = 0; b < BATCH; b++) {
        // ======================= Phase 1 =======================
        if (bid < 64) {
            // A: partial GEMV1, slice sl covers j in [sl*4, sl*4+4)
            const int sl = bid >> 3;                 // 0..7
            const int j0 = sl * 4;
            const int h  = ((bid & 7) << 10) + tid;
            if (tid < 4) sbuf[tid] = sigm(x[(size_t)b * INDIM + j0 + tid]);
            __syncthreads();
            float acc = 0.f;
            #pragma unroll
            for (int r = 0; r < 4; r++)
                acc += sbuf[r] * Wih[(size_t)(j0 + r) * HID + h];
            g_part1[sl * HID + h] = acc;
        } else if (bid < 96) {
            // C: local proof for 4 hidden rows + partial GEMV2
            const int cb  = bid - 64;                // 0..31
            const int h0c = cb * 4;
            if (tid < 32) sbuf[tid] = sigm(x[(size_t)b * INDIM + tid]);
            __syncthreads();
            if (tid < 128) {
                const int hl = tid >> 5, j = tid & 31;
                float v = sbuf[j] * Wih[(size_t)j * HID + h0c + hl];
                #pragma unroll
                for (int off = 16; off; off >>= 1)
                    v += __shfl_down_sync(0xffffffffu, v, off);
                if ((tid & 31) == 0) {
                    // b==0: state init runs concurrently -> active by definition
                    int act = (b == 0) ? 1 : __ldcg(&g_acth[h0c + hl]);
                    sflag[hl] = (act && v >= THRC) ? 1.0f : 0.0f;
                }
            }
            __syncthreads();
            const float f0 = sflag[0], f1 = sflag[1], f2 = sflag[2], f3 = sflag[3];
            const int o = tid;
            float acc = f0 * Who[(size_t)(h0c + 0) * OUTDIM + o]
                      + f1 * Who[(size_t)(h0c + 1) * OUTDIM + o]
                      + f2 * Who[(size_t)(h0c + 2) * OUTDIM + o]
                      + f3 * Who[(size_t)(h0c + 3) * OUTDIM + o];
            g_part2[cb * OUTDIM + o] = acc;
        } else {
            if (b == 0) {
                float4 z = make_float4(0.f, 0.f, 0.f, 0.f);
                for (int i = (bid - 96) * NT + tid; i < (BATCH * OUTDIM / 4); i += 52 * NT)
                    ((float4*)out)[i] = z;
                const int g = (bid - 96) * NT + tid;
                if (g < HID)               { g_vh[g] = 0.f; g_acth[g] = 1; }
                else if (g < HID + OUTDIM) { g_vo[g - HID] = 0.f; g_acto[g - HID] = 1; }
            }
            if (bid == 147 && tid == 0) {
                if (b == 0) g_cnt_act = HID;
                g_cnt_spk = 0; g_need_full = 0; g_retry = 0;
            }
        }
        grid_barrier();   // bar1

        // ======================= Phase 2 =======================
        if (bid < 8) {
            // B: global hidden decisions
            const int h = (bid << 10) + tid;
            float c = 0.f;
            #pragma unroll
            for (int sl = 0; sl < 8; sl++) c += __ldcg(&g_part1[sl * HID + h]);
            const int act = __ldcg(&g_acth[h]);
            const bool spike = act && (c >= THRM);
            const bool needf = act && !spike;
            if (spike) g_acth[h] = 0;
            g_hflag[h] = spike ? 1.0f : 0.0f;
            unsigned ms = __ballot_sync(0xffffffffu, spike);
            if ((tid & 31) == 0 && ms) {
                atomicAdd(&g_cnt_spk, __popc(ms));
                atomicSub(&g_cnt_act, __popc(ms));
            }
            unsigned mf = __ballot_sync(0xffffffffu, needf);
            if ((tid & 31) == 0 && mf) g_need_full = 1;
        } else if (bid == 8) {
            // D: output decisions from lower-bound partials
            const int o = tid;
            float cp = 0.f;
            #pragma unroll
            for (int sl = 0; sl < 32; sl++) cp += __ldcg(&g_part2[sl * OUTDIM + o]);
            cp *= 0.1f;
            const int act = __ldcg(&g_acto[o]);
            const bool spike = act && (cp >= THRM);
            const bool undec = act && !spike;
            if (spike) { out[(size_t)b * OUTDIM + o] = 0.1f; g_acto[o] = 0; }
            unsigned mu = __ballot_sync(0xffffffffu, undec);
            if ((tid & 31) == 0 && mu) g_retry = 1;
        }
        grid_barrier();   // bar2

        int need_full = __ldcg(&g_need_full);
        int retry     = __ldcg(&g_retry);

        if (!need_full && !retry) {           // common path
            if (__ldcg(&g_cnt_act) == 0) return;   // rows prefilled to 0
            continue;
        }

        // ---------- hidden fallback: full GEMV1 + exact dynamics ----------
        if (need_full) {
            if (bid < 128) {
                const int slice = bid >> 3;
                const int j0    = slice << 8;
                const int h     = ((bid & 7) << 10) + tid;
                if (tid < 256) sbuf[tid] = sigm(x[(size_t)b * INDIM + j0 + tid]);
                __syncthreads();
                const float* wp = Wih + (size_t)j0 * HID + h;
                float acc = 0.f;
                #pragma unroll 8
                for (int j = 0; j < 256; j++) acc += sbuf[j] * wp[(size_t)j * HID];
                g_part1[slice * HID + h] = acc;
            }
            grid_barrier();
            if (bid < 8) {
                const int h = (bid << 10) + tid;
                const int act = __ldcg(&g_acth[h]);
                float c = 0.f;
                #pragma unroll
                for (int sl = 0; sl < 16; sl++) c += __ldcg(&g_part1[sl * HID + h]);
                float v = g_vh[h];
                float hf = 0.f;
                #pragma unroll
                for (int t = 0; t < TSTEPS; t++) {
                    v = v * LEAK + c;
                    if (v >= 1.0f) { hf = 1.f; break; }
                }
                const bool spike = act && (hf != 0.f);
                if (spike)    { g_acth[h] = 0; g_hflag[h] = 1.0f; }
                else if (act) g_vh[h] = v;     // exact membrane carry
                unsigned ms = __ballot_sync(0xffffffffu, spike);
                if ((tid & 31) == 0 && ms) {
                    atomicAdd(&g_cnt_spk, __popc(ms));
                    atomicSub(&g_cnt_act, __popc(ms));
                }
            }
            grid_barrier();
            retry = 1;   // flags may have changed; recompute remaining outputs
        }

        // ---------- output fallback: exact currents + dynamics ----------
        if (retry) {
            const int S = __ldcg(&g_cnt_spk);
            if (S > 0) {
                if (bid < 128) {
                    if (tid < 64) sbuf[tid] = __ldcg(&g_hflag[bid * 64 + tid]);
                    __syncthreads();
                    const float* wp = Who + (size_t)bid * 64 * OUTDIM + tid;
                    float acc = 0.f;
                    #pragma unroll 8
                    for (int k = 0; k < 64; k++) acc += sbuf[k] * wp[(size_t)k * OUTDIM];
                    g_part2[bid * OUTDIM + tid] = acc;
                }
                grid_barrier();
                if (bid == 8) {
                    const int o = tid;
                    float cf = 0.f;
                    #pragma unroll
                    for (int sl = 0; sl < 128; sl++) cf += __ldcg(&g_part2[sl * OUTDIM + o]);
                    cf *= 0.1f;
                    if (__ldcg(&g_acto[o])) {
                        float v = g_vo[o];
                        float of = 0.f;
                        #pragma unroll
                        for (int t = 0; t < TSTEPS; t++) {
                            v = v * LEAK + cf;
                            if (v >= 1.0f) { of = 1.f; break; }
                        }
                        if (of != 0.f) { out[(size_t)b * OUTDIM + o] = 0.1f; g_acto[o] = 0; }
                        else           g_vo[o] = v;
                    }
                }
            } else {
                // no hidden spike this batch: cur_o == 0 exactly -> pure decay
                if (bid == 8 && __ldcg(&g_acto[tid])) g_vo[tid] *= LEAK10;
            }
            grid_barrier();
        }

        if (__ldcg(&g_cnt_act) == 0) return;
    }
}

extern "C" void kernel_launch(void* const* d_in, const int* in_sizes, int n_in,
                              void* d_out, int out_size) {
    const float* x   = (const float*)d_in[0];
    const float* Wih = (const float*)d_in[1];
    const float* Who = (const float*)d_in[2];
    (void)in_sizes; (void)n_in; (void)out_size;
    snn_kernel<<<NB, NT>>>(x, Wih, Who, (float*)d_out);
}

// round 8
// speedup vs baseline: 4.3600x; 1.0175x over previous
#include <cuda_runtime.h>

// NeuromorphicNetwork — exact-decision shortcut kernel, v4.
// One sync point per batch: last-arriving block decides inside the barrier.
//
// Proven facts (rounds 1-3):
//  1) "time" = spike_count => every neuron spikes at most once ever; threshold
//     never adapts (stays 1.0).
//  2) W_ih, W_ho in [0,1], drives (sigmoid(x), flags) >= 0 => any partial
//     current sum is a LOWER BOUND. partial >= THRM (margin covering FP
//     reorder) => reference also spikes, at step 0, exactly.
//  3) Bernoulli sampling -> expectation sigmoid(x): currents ~1024 vs thr 1.
//
// v4 layout: 32 blocks x 1024 threads. Block i OWNS hidden slice
// [i*256, i*256+256): it reads 32 j-rows of W_ih for its columns (32 KB),
// decides its hidden spikes locally (no cross-block reduction), keeps
// g_acth/g_vh for its slice, and emits a GEMV2 partial for its first 4 rows
// (128-row W_ho subsample, flags known in-block). The custom barrier's
// releaser block then reduces the 32 partial slices, makes output decisions,
// writes the row, and publishes a status word before releasing everyone.
// Exit when no hidden neuron remains active (future rows provably 0,
// prefilled at b==0). Undecidable neurons trigger exact full-GEMV fallbacks
// with membrane-potential carry (never taken on this data).

#define NB 32
#define NT 1024
#define BATCH 512
#define INDIM 4096
#define HID 8192
#define OUTDIM 1024
#define HSL 256                      // hidden columns per block
#define TSTEPS 10
#define LEAK 0.95f
#define LEAK10 0.5987369392383789f   // 0.95^10
#define THRM 1.002f                  // provable-spike margin (worst-case FP reorder)

#define ST_CONT 0
#define ST_EXIT 1
#define ST_FB1  2   // hidden fallback (then output fallback)
#define ST_FB2  3   // output fallback only

// -------- static scratch --------
__device__ float g_part2[NB * OUTDIM];
__device__ int   g_blk_spk[NB];     // spikes this batch, per block
__device__ int   g_blk_act[NB];     // remaining active hidden, per block
__device__ int   g_blk_nf[NB];      // need-full flag, per block
__device__ float g_vh[HID];
__device__ int   g_acth[HID];
__device__ float g_hflag[HID];
__device__ float g_vo[OUTDIM];
__device__ int   g_acto[OUTDIM];
__device__ int   g_status;
__device__ unsigned g_bar_cnt;
__device__ volatile unsigned g_bar_gen;

__device__ __forceinline__ void grid_barrier() {
    __threadfence();
    __syncthreads();
    if (threadIdx.x == 0) {
        unsigned gen = g_bar_gen;
        if (atomicAdd(&g_bar_cnt, 1u) == NB - 1u) {
            g_bar_cnt = 0;
            __threadfence();
            g_bar_gen = gen + 1u;
        } else {
            while (g_bar_gen == gen) __nanosleep(32);
        }
    }
    __syncthreads();
}

__device__ __forceinline__ float sigm(float v) {
    return 1.0f / (1.0f + __expf(-v));
}

__device__ __forceinline__ int warp_sum(int v) {
    #pragma unroll
    for (int off = 16; off; off >>= 1) v += __shfl_down_sync(0xffffffffu, v, off);
    return v;
}

extern "C" __global__ void __launch_bounds__(NT, 1)
snn_kernel(const float* __restrict__ x,
           const float* __restrict__ Wih,
           const float* __restrict__ Who,
           float* __restrict__ out)
{
    __shared__ float ssm[INDIM];     // sigmoid(x): first 32 common / all fallback
    __shared__ float spart[NT];      // j-group partials / hflag cache (fallback)
    __shared__ float sflag[4];       // flags of this block's 4 sampled rows
    __shared__ int   scnt[3];        // spk, act, nf accumulators
    __shared__ int   sIsLast, sRetry, sS, sNF, sACT;
    __shared__ unsigned sGen;

    const int i   = blockIdx.x;
    const int tid = threadIdx.x;
    const int h0  = i * HSL;
    const int hl  = tid & (HSL - 1);
    const int jg  = tid >> 8;        // 0..3 j-groups

    for (int b = 0; b < BATCH; b++) {
        // ================= Phase 1 (all work block-local) =================
        if (b == 0) {
            // prefill out with zeros (out poisoned 0xAA): 4096 float4 / block
            float4 z = make_float4(0.f, 0.f, 0.f, 0.f);
            const int base = i * 4096;
            #pragma unroll
            for (int r = 0; r < 4; r++)
                ((float4*)out)[base + r * NT + tid] = z;
            if (tid < HSL) g_vh[h0 + tid] = 0.f;   // own-slice membrane init
        }
        if (tid < 32) ssm[tid] = sigm(x[(size_t)b * INDIM + tid]);
        if (tid < 3)  scnt[tid] = 0;
        __syncthreads();

        // partial GEMV1 for own slice: 32 j-rows, 4 j-groups x 8
        {
            float acc = 0.f;
            #pragma unroll
            for (int r = 0; r < 8; r++) {
                int j = jg * 8 + r;
                acc += ssm[j] * Wih[(size_t)j * HID + h0 + hl];
            }
            spart[tid] = acc;
        }
        __syncthreads();

        // local hidden decisions (sole prover for this slice)
        if (tid < HSL) {
            float c = spart[hl] + spart[HSL + hl] + spart[2 * HSL + hl] + spart[3 * HSL + hl];
            int  act   = (b == 0) ? 1 : g_acth[h0 + hl];   // own-block state
            bool spike = act && (c >= THRM);                // lower bound >= thr
            bool needf = act && !spike;                     // undecidable -> exact
            g_acth[h0 + hl]  = (act && !spike) ? 1 : 0;
            g_hflag[h0 + hl] = spike ? 1.0f : 0.0f;
            if (hl < 4) sflag[hl] = spike ? 1.0f : 0.0f;
            unsigned ms = __ballot_sync(0xffffffffu, spike);
            unsigned ma = __ballot_sync(0xffffffffu, act && !spike);
            unsigned mf = __ballot_sync(0xffffffffu, needf);
            if ((tid & 31) == 0) {
                atomicAdd(&scnt[0], __popc(ms));
                atomicAdd(&scnt[1], __popc(ma));
                atomicAdd(&scnt[2], __popc(mf));
            }
        }
        __syncthreads();
        if (tid == 0) {
            g_blk_spk[i] = scnt[0];
            g_blk_act[i] = scnt[1];
            g_blk_nf[i]  = scnt[2];
        }

        // GEMV2 partial: this block's 4 sampled W_ho rows (flags local)
        {
            float f0 = sflag[0], f1 = sflag[1], f2 = sflag[2], f3 = sflag[3];
            float a = f0 * Who[(size_t)(h0 + 0) * OUTDIM + tid]
                    + f1 * Who[(size_t)(h0 + 1) * OUTDIM + tid]
                    + f2 * Who[(size_t)(h0 + 2) * OUTDIM + tid]
                    + f3 * Who[(size_t)(h0 + 3) * OUTDIM + tid];
            g_part2[i * OUTDIM + tid] = a;
        }

        // ================= barrier + decide (single sync point) =================
        __threadfence();
        __syncthreads();
        if (tid == 0) {
            unsigned gen = g_bar_gen;
            sGen = gen;
            sIsLast = (atomicAdd(&g_bar_cnt, 1u) == NB - 1u) ? 1 : 0;
        }
        __syncthreads();

        if (sIsLast) {
            __threadfence();                     // all other blocks' writes visible
            if (tid == 0) sRetry = 0;
            {
                int vS = 0, vA = 0, vN = 0;
                if (tid < NB) {
                    vS = __ldcg(&g_blk_spk[tid]);
                    vA = __ldcg(&g_blk_act[tid]);
                    vN = __ldcg(&g_blk_nf[tid]);
                }
                if (tid < 32) { vS = warp_sum(vS); vA = warp_sum(vA); vN = warp_sum(vN); }
                if (tid == 0) { sS = vS; sACT = vA; sNF = vN; }
            }
            __syncthreads();

            const int o = tid;
            int act_o = (b == 0) ? 1 : __ldcg(&g_acto[o]);  // may be written by other blocks
            if (sS == 0) {
                // no hidden spike: cur_o == 0 exactly -> pure decay, no output spike
                float v = (b == 0) ? 0.f : __ldcg(&g_vo[o]);
                if (act_o) g_vo[o] = v * LEAK10;
                if (b == 0) g_acto[o] = 1;
            } else {
                float cp = 0.f;
                #pragma unroll
                for (int k = 0; k < NB; k++) cp += __ldcg(&g_part2[k * OUTDIM + o]);
                cp *= 0.1f;                                  // lower bound of cur_o
                bool spike = act_o && (cp >= THRM);
                bool undec = act_o && !spike;
                if (spike) out[(size_t)b * OUTDIM + o] = 0.1f;
                g_acto[o] = (act_o && !spike) ? 1 : 0;
                if (b == 0) g_vo[o] = 0.f;                   // init for potential fallback
                unsigned mu = __ballot_sync(0xffffffffu, undec);
                if ((tid & 31) == 0 && mu) sRetry = 1;
            }
            __syncthreads();
            if (tid == 0) {
                g_status = sNF ? ST_FB1 : (sRetry ? ST_FB2 : (sACT == 0 ? ST_EXIT : ST_CONT));
                g_bar_cnt = 0;
                __threadfence();
                g_bar_gen = sGen + 1u;                       // release
            }
        } else {
            if (tid == 0) { while (g_bar_gen == sGen) __nanosleep(32); }
            __syncthreads();
        }
        __threadfence();
        const int st = __ldcg(&g_status);

        if (st == ST_EXIT) return;       // remaining rows prefilled to 0
        if (st == ST_CONT) continue;

        // ============ fallback: hidden exact (full GEMV1 + dynamics) ============
        if (st == ST_FB1) {
            for (int t = tid; t < INDIM; t += NT)
                ssm[t] = sigm(x[(size_t)b * INDIM + t]);
            __syncthreads();
            float acc = 0.f;
            #pragma unroll 8
            for (int j = jg * 1024; j < jg * 1024 + 1024; j++)
                acc += ssm[j] * Wih[(size_t)j * HID + h0 + hl];
            spart[tid] = acc;
            __syncthreads();
            if (tid < 2) scnt[tid] = 0;
            __syncthreads();
            if (tid < HSL) {
                float c = spart[hl] + spart[HSL + hl] + spart[2 * HSL + hl] + spart[3 * HSL + hl];
                int   act = g_acth[h0 + hl];
                float v   = g_vh[h0 + hl];
                float hf  = 0.f;
                #pragma unroll
                for (int t = 0; t < TSTEPS; t++) {
                    v = v * LEAK + c;
                    if (v >= 1.0f) { hf = 1.f; break; }
                }
                bool spike = act && (hf != 0.f);
                if (spike)    { g_acth[h0 + hl] = 0; g_hflag[h0 + hl] = 1.0f; }
                else if (act) g_vh[h0 + hl] = v;             // exact membrane carry
                unsigned ms = __ballot_sync(0xffffffffu, spike);
                unsigned ma = __ballot_sync(0xffffffffu, act && !spike);
                if ((tid & 31) == 0) {
                    atomicAdd(&scnt[0], __popc(ms));
                    atomicAdd(&scnt[1], __popc(ma));
                }
            }
            __syncthreads();
            if (tid == 0) {
                g_blk_spk[i] += scnt[0];
                g_blk_act[i]  = scnt[1];
            }
            grid_barrier();
        }

        // ============ fallback: output exact (full GEMV2 + dynamics) ============
        {
            if (tid < HSL) spart[tid] = g_hflag[h0 + tid];   // own slice
            __syncthreads();
            float a = 0.f;
            #pragma unroll 8
            for (int r = 0; r < HSL; r++)
                a += spart[r] * Who[(size_t)(h0 + r) * OUTDIM + tid];
            g_part2[i * OUTDIM + tid] = a;
            grid_barrier();

            if (i == 0) {
                const int o = tid;
                float cf = 0.f;
                #pragma unroll
                for (int k = 0; k < NB; k++) cf += __ldcg(&g_part2[k * OUTDIM + o]);
                cf *= 0.1f;
                if (__ldcg(&g_acto[o])) {
                    float v  = __ldcg(&g_vo[o]);
                    float of = 0.f;
                    #pragma unroll
                    for (int t = 0; t < TSTEPS; t++) {
                        v = v * LEAK + cf;
                        if (v >= 1.0f) { of = 1.f; break; }
                    }
                    if (of != 0.f) { out[(size_t)b * OUTDIM + o] = 0.1f; g_acto[o] = 0; }
                    else           g_vo[o] = v;
                }
            }
            grid_barrier();

            // uniform exit check (g_blk_act written before previous barriers)
            int vA = 0;
            if (tid < NB) vA = __ldcg(&g_blk_act[tid]);
            if (tid < 32) vA = warp_sum(vA);
            if (tid == 0) sACT = vA;
            __syncthreads();
            if (sACT == 0) return;
        }
    }
}

extern "C" void kernel_launch(void* const* d_in, const int* in_sizes, int n_in,
                              void* d_out, int out_size) {
    const float* x   = (const float*)d_in[0];
    const float* Wih = (const float*)d_in[1];
    const float* Who = (const float*)d_in[2];
    (void)in_sizes; (void)n_in; (void)out_size;
    snn_kernel<<<NB, NT>>>(x, Wih, Who, (float*)d_out);
}

// round 9
// speedup vs baseline: 5.1905x; 1.1905x over previous
#include <cuda_runtime.h>

// NeuromorphicNetwork — exact-decision shortcut kernel, v5.
// Minimal-round-trip design: one fused load phase, RED-accumulated partials,
// status packed into the release word, out-prefill after release.
//
// Proven facts (rounds 1-3):
//  1) "time" = spike_count => every neuron spikes at most once ever; threshold
//     never adapts (stays 1.0).
//  2) W_ih, W_ho in [0,1], drives (sigmoid(x), flags) >= 0 => any partial
//     current sum is a LOWER BOUND. partial >= THRM (margin >> FP reorder
//     error) => the reference also spikes, at step 0, exactly.
//  3) Bernoulli sampling -> expectation sigmoid(x): currents ~1024 vs thr 1.
//
// 32 blocks x 1024 threads. Block i owns hidden slice [i*256, i*256+256):
// 32-j-row partial current decides spikes locally (partial proves ONLY
// spikes; any remaining-active neuron is undecidable -> exact FB1 fallback).
// Block's first-4-rows W_ho partial is RED-added to g_acc. Last-arriving
// block reduces, decides outputs, writes the full row, publishes
// (epoch<<2)|status. EXIT => blocks fill remaining rows with 0 and return.

#define NB 32
#define NT 1024
#define BATCH 512
#define INDIM 4096
#define HID 8192
#define OUTDIM 1024
#define HSL 256
#define TSTEPS 10
#define LEAK 0.95f
#define THRM 1.002f

#define ST_EXIT 1u
#define ST_FB1  2u
#define ST_FB2  3u

// -------- static scratch (zero-init at load; invariants restored each launch) --------
__device__ float g_acc[OUTDIM];              // RED partial accumulator (0 between batches)
__device__ unsigned long long g_cnt;         // packed spk | rem<<20      (0 between batches)
__device__ unsigned g_arr;                   // arrivals                  (0 between batches)
__device__ volatile unsigned g_rel;          // monotonic (epoch<<2)|status
__device__ float g_part2[NB * OUTDIM];       // FB only
__device__ float g_vh[HID];                  // FB only (membrane carry)
__device__ float g_vo[OUTDIM];               // FB only
__device__ int   g_acto[OUTDIM];
__device__ unsigned g_fbw;                   // FB exit word (written+read between barriers)
__device__ unsigned g_b2cnt;
__device__ volatile unsigned g_b2gen;

__device__ __forceinline__ void grid_barrier2() {
    __threadfence();
    __syncthreads();
    if (threadIdx.x == 0) {
        unsigned gen = g_b2gen;
        if (atomicAdd(&g_b2cnt, 1u) == NB - 1u) {
            g_b2cnt = 0;
            __threadfence();
            g_b2gen = gen + 1u;
        } else {
            while (g_b2gen == gen) { }
        }
    }
    __syncthreads();
}

__device__ __forceinline__ float sigm(float v) {
    return 1.0f / (1.0f + __expf(-v));
}

extern "C" __global__ void __launch_bounds__(NT, 1)
snn_kernel(const float* __restrict__ x,
           const float* __restrict__ Wih,
           const float* __restrict__ Who,
           float* __restrict__ out)
{
    __shared__ float spart[NT];
    __shared__ float sflag[HSL];     // this block's hidden spike flags (persist)
    __shared__ int   sact[HSL];      // this block's active bits (persist)
    __shared__ int   scnt[2];        // spk, rem
    __shared__ unsigned sSamp, sStat;
    __shared__ int   sLast, sRetry, sS, sREM;
    __shared__ float ssm[INDIM];     // FB1 only

    const int i    = blockIdx.x;
    const int tid  = threadIdx.x;
    const int jg   = tid >> 8;       // 0..3
    const int hl   = tid & (HSL - 1);
    const int lane = tid & 31;
    const int h0   = i * HSL;

    for (int b = 0; b < BATCH; b++) {
        // ---------------- phase 1: fused loads + local decisions ----------------
        if (tid == 0) { sSamp = g_rel; sRetry = 0; }   // pre-arrival sample
        if (tid < 2) scnt[tid] = 0;
        if (b == 0 && tid < HSL) sact[tid] = 1;

        // all global loads issued together (independent): x, Wih x8, Who x4
        float sj = 0.f;
        if (lane < 8) sj = x[(size_t)b * INDIM + jg * 8 + lane];
        float w[8];
        #pragma unroll
        for (int r = 0; r < 8; r++)
            w[r] = Wih[(size_t)(jg * 8 + r) * HID + h0 + hl];
        float who[4];
        #pragma unroll
        for (int r = 0; r < 4; r++)
            who[r] = Who[(size_t)(h0 + r) * OUTDIM + tid];

        sj = sigm(sj);
        float acc = 0.f;
        #pragma unroll
        for (int r = 0; r < 8; r++)
            acc += __shfl_sync(0xffffffffu, sj, r) * w[r];
        spart[tid] = acc;
        __syncthreads();

        if (tid < HSL) {
            float c = spart[tid] + spart[HSL + tid] + spart[2 * HSL + tid] + spart[3 * HSL + tid];
            int  act   = sact[tid];
            bool spike = act && (c >= THRM);   // lower bound proves spike
            bool rem   = act && !spike;        // undecidable -> exact fallback
            sact[tid]  = rem ? 1 : 0;
            sflag[tid] = spike ? 1.0f : 0.0f;
            unsigned ms = __ballot_sync(0xffffffffu, spike);
            unsigned mr = __ballot_sync(0xffffffffu, rem);
            if (lane == 0) {
                if (ms) atomicAdd(&scnt[0], __popc(ms));
                if (mr) atomicAdd(&scnt[1], __popc(mr));
            }
        }
        __syncthreads();

        // GEMV2 partial from this block's 4 sampled rows -> RED accumulate
        {
            float p = sflag[0] * who[0] + sflag[1] * who[1]
                    + sflag[2] * who[2] + sflag[3] * who[3];
            if (p != 0.f) atomicAdd(&g_acc[tid], p);
        }
        if (tid == 0) {
            unsigned long long packed =
                (unsigned long long)scnt[0] | ((unsigned long long)scnt[1] << 20);
            if (packed) atomicAdd(&g_cnt, packed);
        }

        // ---------------- single sync point: arrive; last block decides ----------------
        __threadfence();
        __syncthreads();
        if (tid == 0) sLast = (atomicAdd(&g_arr, 1u) == NB - 1u) ? 1 : 0;
        __syncthreads();

        unsigned status;
        if (sLast) {
            __threadfence();   // all blocks' REDs visible
            if (tid == 0) {
                unsigned long long cc = __ldcg(&g_cnt);
                sS   = (int)(cc & 0xFFFFFu);
                sREM = (int)(cc >> 20);
            }
            __syncthreads();
            const int S = sS, REM = sREM;
            const int o = tid;
            float a = __ldcg(&g_acc[o]);
            g_acc[o] = 0.f;                               // restore invariant
            int  act_o  = (b == 0) ? 1 : __ldcg(&g_acto[o]);
            bool spike_o = false, undec = false;
            if (S > 0) {
                float cp = 0.1f * a;                      // lower bound of cur_o
                spike_o = act_o && (cp >= THRM);
                undec   = act_o && !spike_o;
            }
            out[(size_t)b * OUTDIM + o] = spike_o ? 0.1f : 0.0f;   // full row
            unsigned mu = __ballot_sync(0xffffffffu, undec);
            if (lane == 0 && mu) sRetry = 1;
            __syncthreads();
            status = REM ? ST_FB1 : (sRetry ? ST_FB2 : ST_EXIT);
            if (status != ST_EXIT)
                g_acto[o] = (act_o && !spike_o) ? 1 : 0;  // FB paths need it
            if (tid == 0) { g_cnt = 0ull; g_arr = 0u; }   // restore invariants
            __threadfence();
            __syncthreads();
            if (tid == 0) g_rel = ((sSamp & ~3u) + 4u) | status;   // release
        } else {
            if (tid == 0) {
                unsigned v;
                do { v = g_rel; } while (((v ^ sSamp) & ~3u) == 0u);
                sStat = v & 3u;
            }
            __syncthreads();
            status = sStat;
        }

        if (status == ST_EXIT) {
            // all hidden inactive forever => cur_h=0 => no future spikes;
            // un-spiked outputs only decay (v<1) => all remaining rows are 0.
            float4 z = make_float4(0.f, 0.f, 0.f, 0.f);
            const int start = (b + 1) * (OUTDIM / 4);
            const int total = BATCH * (OUTDIM / 4);
            for (int idx = start + i * NT + tid; idx < total; idx += NB * NT)
                ((float4*)out)[idx] = z;
            return;
        }

        // ============ FB1: exact hidden (full GEMV1 + 10-step dynamics) ============
        if (status == ST_FB1) {
            for (int t = tid; t < INDIM; t += NT)
                ssm[t] = sigm(x[(size_t)b * INDIM + t]);
            __syncthreads();
            float acc2 = 0.f;
            #pragma unroll 8
            for (int j = jg * 1024; j < jg * 1024 + 1024; j++)
                acc2 += ssm[j] * Wih[(size_t)j * HID + h0 + hl];
            spart[tid] = acc2;
            __syncthreads();
            if (tid < HSL) {
                float c = spart[tid] + spart[HSL + tid] + spart[2 * HSL + tid] + spart[3 * HSL + tid];
                int   act = sact[tid];
                float v   = (b == 0) ? 0.f : g_vh[h0 + tid];
                float hf  = 0.f;
                #pragma unroll
                for (int t = 0; t < TSTEPS; t++) {
                    v = v * LEAK + c;
                    if (v >= 1.0f) { hf = 1.f; break; }
                }
                bool spike = act && (hf != 0.f);
                if (spike)    { sact[tid] = 0; sflag[tid] = 1.0f; }
                else if (act) g_vh[h0 + tid] = v;    // exact membrane carry
            }
            __syncthreads();
        }

        // ============ FB2 stage: exact outputs (runs for FB1 and FB2) ============
        {
            // recount remaining active hidden (g_cnt was reset by releaser)
            if (tid == 0) scnt[0] = 0;
            __syncthreads();
            if (tid < HSL) {
                unsigned ma = __ballot_sync(0xffffffffu, sact[tid] != 0);
                if (lane == 0 && ma) atomicAdd(&scnt[0], __popc(ma));
            }
            __syncthreads();
            if (tid == 0 && scnt[0])
                atomicAdd(&g_cnt, (unsigned long long)scnt[0]);

            // full GEMV2 partial: this block's 256 W_ho rows with its flags
            float pa = 0.f;
            #pragma unroll 8
            for (int r = 0; r < HSL; r++)
                pa += sflag[r] * Who[(size_t)(h0 + r) * OUTDIM + tid];
            g_part2[i * OUTDIM + tid] = pa;
            grid_barrier2();

            if (i == 0) {
                const int o = tid;
                float cf = 0.f;
                #pragma unroll
                for (int k = 0; k < NB; k++) cf += __ldcg(&g_part2[k * OUTDIM + o]);
                cf *= 0.1f;
                if (__ldcg(&g_acto[o])) {
                    float v  = (b == 0) ? 0.f : __ldcg(&g_vo[o]);
                    float of = 0.f;
                    #pragma unroll
                    for (int t = 0; t < TSTEPS; t++) {
                        v = v * LEAK + cf;
                        if (v >= 1.0f) { of = 1.f; break; }
                    }
                    if (of != 0.f) { out[(size_t)b * OUTDIM + o] = 0.1f; g_acto[o] = 0; }
                    else           g_vo[o] = v;
                }
                if (tid == 0) {
                    unsigned long long cc = __ldcg(&g_cnt);
                    g_fbw = (cc == 0ull) ? 1u : 0u;      // exit?
                    g_cnt = 0ull;                         // restore invariant
                }
            }
            grid_barrier2();

            if (__ldcg(&g_fbw)) {
                float4 z = make_float4(0.f, 0.f, 0.f, 0.f);
                const int start = (b + 1) * (OUTDIM / 4);
                const int total = BATCH * (OUTDIM / 4);
                for (int idx = start + i * NT + tid; idx < total; idx += NB * NT)
                    ((float4*)out)[idx] = z;
                return;
            }
        }
    }
}

extern "C" void kernel_launch(void* const* d_in, const int* in_sizes, int n_in,
                              void* d_out, int out_size) {
    const float* x   = (const float*)d_in[0];
    const float* Wih = (const float*)d_in[1];
    const float* Who = (const float*)d_in[2];
    (void)in_sizes; (void)n_in; (void)out_size;
    snn_kernel<<<NB, NT>>>(x, Wih, Who, (float*)d_out);
}

// round 10
// speedup vs baseline: 6.4354x; 1.2399x over previous
#include <cuda_runtime.h>

// NeuromorphicNetwork — exact-decision shortcut, v6: single-prover design.
//
// Proven facts (rounds 1-5):
//  1) "time" = spike_count => every neuron spikes at most once ever; threshold
//     never adapts (stays 1.0).
//  2) W_ih, W_ho in [0,1], drives (sigmoid(x), spike flags) >= 0 => any
//     partial current sum is a LOWER BOUND of the full current. partial >=
//     THRM=1.002 (margin >> FP reorder error) => the reference also spikes,
//     at step 0, exactly.
//  3) Bernoulli sampling -> expectation sigmoid(x): currents ~1024 vs thr 1.
//  4) NEW: if ALL 1024 outputs provably spike at b=0 they are inactive
//     forever => rows 1..511 are exactly 0 INDEPENDENT of hidden state.
//     Block 0 alone can prove this: its 32 proven hidden rows give
//     cur_o lower bound ~1.6 >= 1.002 for every output.
//
// Common path (no grid barrier):
//   block 0 : prove 32 hidden spikes (32x32 Wih = 4KB), prove all 1024
//             outputs (32 Who rows = 128KB), write row 0 = 0.1, publish.
//   blocks 1..31 : check-in (epoch-race guard), prefill rows 1..511 with 0,
//             poll status, exit.
// Any failed proof -> status FB: ALL blocks run the exact coordinated
// simulation from b=0 (full GEMVs, 10-step dynamics, membrane carry),
// overwriting every row it processes. Never taken on this data.

#define NB 32
#define NT 1024
#define BATCH 512
#define INDIM 4096
#define HID 8192
#define OUTDIM 1024
#define HSL 256
#define TSTEPS 10
#define LEAK 0.95f
#define THRM 1.002f

#define ST_EXIT 1u
#define ST_FB   2u

// -------- static scratch (zero-init at load; invariants restored per launch) --------
__device__ unsigned g_arr;                 // check-ins (0 between launches)
__device__ volatile unsigned g_rel;        // monotonic (epoch<<2)|status
__device__ float g_part2[NB * OUTDIM];     // fallback only
__device__ int   g_blk_act[NB];            // fallback only
__device__ unsigned g_fbw;                 // fallback exit word
__device__ unsigned g_b2cnt;
__device__ volatile unsigned g_b2gen;

__device__ __forceinline__ void grid_barrier2() {
    __threadfence();
    __syncthreads();
    if (threadIdx.x == 0) {
        unsigned gen = g_b2gen;
        if (atomicAdd(&g_b2cnt, 1u) == NB - 1u) {
            g_b2cnt = 0;
            __threadfence();
            g_b2gen = gen + 1u;
        } else {
            while (g_b2gen == gen) __nanosleep(64);
        }
    }
    __syncthreads();
}

__device__ __forceinline__ float sigm(float v) {
    return 1.0f / (1.0f + __expf(-v));
}

extern "C" __global__ void __launch_bounds__(NT, 1)
snn_kernel(const float* __restrict__ x,
           const float* __restrict__ Wih,
           const float* __restrict__ Who,
           float* __restrict__ out)
{
    __shared__ float ssm[INDIM];      // fast: first 32 / fallback: all
    __shared__ float spart[NT];
    __shared__ float sflagB[32];      // block-0 fast-path proven flags
    __shared__ float svh[HSL];        // fallback hidden membrane (persist)
    __shared__ int   sact[HSL];
    __shared__ float sflag[HSL];
    __shared__ float soV[OUTDIM];     // block-0 fallback output state
    __shared__ int   soA[OUTDIM];
    __shared__ unsigned sSamp;
    __shared__ int   sFail, sStat;

    const int tid  = threadIdx.x;
    const int bid  = blockIdx.x;
    const int lane = tid & 31;

    bool to_fallback = false;

    if (bid == 0) {
        // ---------------- the prover ----------------
        if (tid == 0) { sFail = 0; sSamp = g_rel; }
        if (tid < 32) ssm[tid] = sigm(x[tid]);            // batch-0 inputs j<32
        __syncthreads();

        // hidden proofs, h in [0,32): j = tid>>5, h = tid&31 (coalesced)
        spart[tid] = ssm[tid >> 5] * Wih[(size_t)(tid >> 5) * HID + (tid & 31)];
        __syncthreads();
        if (tid < 32) {
            float c = 0.f;
            #pragma unroll
            for (int j = 0; j < 32; j++) c += spart[j * 32 + tid];
            sflagB[tid] = (c >= THRM) ? 1.0f : 0.0f;      // lower bound proves spike
        }
        __syncthreads();

        // output proofs: o = tid, 32 Who rows gated by proven flags
        float cp = 0.f;
        #pragma unroll 8
        for (int r = 0; r < 32; r++)
            cp += sflagB[r] * Who[(size_t)r * OUTDIM + tid];
        cp *= 0.1f;                                       // lower bound of cur_o
        bool ok = (cp >= THRM);
        if (!__all_sync(0xffffffffu, ok) && lane == 0) atomicExch(&sFail, 1);
        __syncthreads();
        const int fail = sFail;

        if (!fail) out[tid] = 0.1f;                       // row 0: all spike, rate 1/10

        // handshake: wait until all waiters sampled (checked in), then publish
        __threadfence();
        __syncthreads();
        if (tid == 0) {
            while (atomicAdd(&g_arr, 0u) != NB - 1u) __nanosleep(32);
            g_arr = 0u;                                   // restore for next launch
            __threadfence();
            g_rel = (((sSamp >> 2) + 1u) << 2) | (fail ? ST_FB : ST_EXIT);
        }
        if (!fail) return;
        to_fallback = true;
    } else {
        // ---------------- the fillers ----------------
        if (tid == 0) {
            sSamp = g_rel;            // sample BEFORE check-in (epoch-race guard)
            __threadfence();
            atomicAdd(&g_arr, 1u);
        }
        // optimistic prefill of rows 1..511 (fallback overwrites every row it runs)
        float4 z = make_float4(0.f, 0.f, 0.f, 0.f);
        for (int idx = (OUTDIM / 4) + (bid - 1) * NT + tid;
             idx < BATCH * (OUTDIM / 4); idx += (NB - 1) * NT)
            ((float4*)out)[idx] = z;
        __syncthreads();
        if (tid == 0) {
            unsigned v;
            for (;;) {
                v = g_rel;
                if ((v ^ sSamp) >> 2) break;
                __nanosleep(64);
            }
            sStat = (int)(v & 3u);
        }
        __syncthreads();
        if (sStat == (int)ST_EXIT) return;
        to_fallback = true;
    }

    // ============ fallback: exact coordinated simulation (never taken) ============
    if (to_fallback) {
        const int h0 = bid * HSL;
        const int jg = tid >> 8;          // 0..3
        const int hl = tid & (HSL - 1);

        for (int b = 0; b < BATCH; b++) {
            if (b == 0) {
                if (tid < HSL) { svh[tid] = 0.f; sact[tid] = 1; }
                if (bid == 0)  { soV[tid] = 0.f; soA[tid] = 1; }
            }
            for (int t = tid; t < INDIM; t += NT)
                ssm[t] = sigm(x[(size_t)b * INDIM + t]);
            __syncthreads();

            // full hidden current for this block's 256-column slice
            float acc = 0.f;
            #pragma unroll 8
            for (int j = jg * 1024; j < jg * 1024 + 1024; j++)
                acc += ssm[j] * Wih[(size_t)j * HID + h0 + hl];
            spart[tid] = acc;
            __syncthreads();

            if (tid < HSL) {
                float c = spart[tid] + spart[HSL + tid]
                        + spart[2 * HSL + tid] + spart[3 * HSL + tid];
                int   act = sact[tid];
                float v   = svh[tid];
                float hf  = 0.f;
                #pragma unroll
                for (int t = 0; t < TSTEPS; t++) {
                    v = v * LEAK + c;
                    if (v >= 1.0f) { hf = 1.f; break; }
                }
                bool sp = act && (hf != 0.f);
                sflag[tid] = sp ? 1.0f : 0.0f;            // this batch's spikes only
                if (sp)       sact[tid] = 0;
                else if (act) svh[tid] = v;               // exact membrane carry
            }
            __syncthreads();
            if (tid == 0) {
                int a = 0;
                for (int r = 0; r < HSL; r++) a += sact[r];
                g_blk_act[bid] = a;
            }

            // full GEMV2 partial for this block's 256 W_ho rows
            float pa = 0.f;
            #pragma unroll 8
            for (int r = 0; r < HSL; r++)
                pa += sflag[r] * Who[(size_t)(h0 + r) * OUTDIM + tid];
            g_part2[bid * OUTDIM + tid] = pa;
            grid_barrier2();

            if (bid == 0) {
                float cf = 0.f;
                #pragma unroll
                for (int k = 0; k < NB; k++) cf += __ldcg(&g_part2[k * OUTDIM + tid]);
                cf *= 0.1f;
                float of = 0.f;
                if (soA[tid]) {
                    float v = soV[tid];
                    #pragma unroll
                    for (int t = 0; t < TSTEPS; t++) {
                        v = v * LEAK + cf;
                        if (v >= 1.0f) { of = 1.f; break; }
                    }
                    if (of != 0.f) soA[tid] = 0;
                    else           soV[tid] = v;
                }
                out[(size_t)b * OUTDIM + tid] = of != 0.f ? 0.1f : 0.0f;  // full row
                if (tid == 0) {
                    int a = 0;
                    for (int k = 0; k < NB; k++) a += __ldcg(&g_blk_act[k]);
                    g_fbw = (a == 0) ? 1u : 0u;
                }
            }
            grid_barrier2();

            // all hidden inactive => future currents 0 => active outputs only
            // decay (v<1) => remaining rows are the prefilled zeros.
            if (__ldcg(&g_fbw)) return;
        }
    }
}

extern "C" void kernel_launch(void* const* d_in, const int* in_sizes, int n_in,
                              void* d_out, int out_size) {
    const float* x   = (const float*)d_in[0];
    const float* Wih = (const float*)d_in[1];
    const float* Who = (const float*)d_in[2];
    (void)in_sizes; (void)n_in; (void)out_size;
    snn_kernel<<<NB, NT>>>(x, Wih, Who, (float*)d_out);
}